// round 15
// baseline (speedup 1.0000x reference)
#include <cuda_runtime.h>

#define THETA 0.9999f
typedef unsigned long long ull;

__device__ __forceinline__ ull pk2(float x, float y) {
    ull r; asm("mov.b64 %0, {%1, %2};" : "=l"(r) : "f"(x), "f"(y)); return r;
}
__device__ __forceinline__ void upk2(float& x, float& y, ull v) {
    asm("mov.b64 {%0, %1}, %2;" : "=f"(x), "=f"(y) : "l"(v));
}
__device__ __forceinline__ ull fma2(ull a, ull b, ull c) {
    ull d; asm("fma.rn.f32x2 %0, %1, %2, %3;" : "=l"(d) : "l"(a), "l"(b), "l"(c)); return d;
}

// IF-neuron spike rate over 50 steps, constant drive a, soft reset.
// Closed form floor(50*a/theta); exact f32 sim only near count boundaries.
__device__ __forceinline__ float rate50(float a) {
    if (a <= 0.0f) return 0.0f;
    if (a >= THETA) return 1.0f;
    float u = a * (50.0f / THETA);
    float k = floorf(u);
    float d = u - k;
    if (d > 1e-4f && d < 0.9999f) {
        return k * 0.02f;
    }
    float v = 0.0f, cnt = 0.0f;
    #pragma unroll
    for (int t = 0; t < 50; ++t) {
        v += a;
        if (v >= THETA) { v -= THETA; cnt += 1.0f; }
    }
    return cnt * 0.02f;
}

// Dynamic shared layout (floats):
//   A  [0,184)        : mx (data at h+1, pads zero); later warp-reduction partials
//   B  [184,4024)     : r1 (16 x stride 184, data at h+1) then r3 (32 x stride 120, data at h+1)
//   C  [4024,9656)    : r2 (32 x stride 176) then r4 (32 x stride 88)
//   W2 [9656,14296)   : w2 staged, 32 rows stride 145 (o*145 + c*9 + k)
//   W3 [14296,21496)  : w3 staged, 32 rows stride 225 (o*225 + c*7 + k)
#define B_OFF   184
#define C_OFF   4024
#define W2_OFF  9656
#define W3_OFF  14296
#define SM_TOTAL 21496
#define SMEM_BYTES (SM_TOTAL * 4)

__global__ __launch_bounds__(256, 2)
void catnet_kernel(const float* __restrict__ x,
                   const float* __restrict__ w1, const float* __restrict__ b1,
                   const float* __restrict__ w2, const float* __restrict__ b2,
                   const float* __restrict__ w3, const float* __restrict__ b3,
                   const float* __restrict__ wf, const float* __restrict__ bf,
                   float* __restrict__ out) {
    extern __shared__ float sm[];
    float* A   = sm;
    float* B   = sm + B_OFF;
    float* C   = sm + C_OFF;
    float* W2s = sm + W2_OFF;
    float* W3s = sm + W3_OFF;
    const int tid = threadIdx.x;
    const int n = blockIdx.x;

    // Stage weights global->shared (issued first; latency overlapped with
    // stages 0-1, complete by the pre-stage-2 barrier).
    #pragma unroll 4
    for (int i = tid; i < 32 * 144; i += 256) {
        int o = i / 144;
        W2s[o * 145 + (i - o * 144)] = w2[i];
    }
    #pragma unroll 4
    for (int i = tid; i < 32 * 224; i += 256) {
        int o = i / 224;
        W3s[o * 225 + (i - o * 224)] = w3[i];
    }

    // zero working region (pad cells + finite values for chunk-tail over-reads)
    for (int i = tid; i < W2_OFF; i += 256) sm[i] = 0.0f;
    __syncthreads();

    // ---- stage 0: mean over time: x[n,0,h,0,t] -> A[h+1] ----
    const float2* xn2 = (const float2*)(x + (long)n * (180 * 50));
    for (int h = tid; h < 180; h += 256) {
        const float2* xp = xn2 + h * 25;
        float s0 = 0.0f, s1 = 0.0f;
        #pragma unroll
        for (int t = 0; t < 25; ++t) {
            float2 v = xp[t];
            s0 += v.x; s1 += v.y;
        }
        A[h + 1] = (s0 + s1) / 50.0f;
    }
    __syncthreads();

    // ---- stage 1: conv (16,1,3) pad 1 + rate -> B (r1, stride 184, data at h+1) ----
    for (int idx = tid; idx < 16 * 180; idx += 256) {
        int o = idx / 180, h = idx - o * 180;
        float a = b1[o]
                + A[h]     * w1[o * 3]
                + A[h + 1] * w1[o * 3 + 1]
                + A[h + 2] * w1[o * 3 + 2];
        B[o * 184 + h + 1] = rate50(a);
    }
    __syncthreads();   // also guarantees weight staging is complete

    // ---- stage 2: conv (32,16,9) pad 1 + rate -> C (r2, stride 176) ----
    // Packed f32x2: even taps -> accE (output pairs (0,1),(2,3),..), odd taps
    // -> accO (output pairs (1,2),(3,4),..); both read 8B-aligned LDS.64 pairs.
    // Output j=0's odd-tap terms accumulate in a scalar.
    {
        int o = tid >> 3;
        int h0 = (tid & 7) * 24;            // even -> aligned ull loads
        float bb = b2[o];
        ull bb2 = pk2(bb, bb);
        ull accE[12], accO[12];
        #pragma unroll
        for (int m = 0; m < 12; ++m) { accE[m] = bb2; accO[m] = 0ULL; }
        float acc0o = 0.0f;
        const float* wrow = W2s + o * 145;
        #pragma unroll 1
        for (int c = 0; c < 16; ++c) {
            const float* row = B + c * 184 + h0;
            const ull* row2 = (const ull*)row;
            ull E[16];
            #pragma unroll
            for (int m = 0; m < 16; ++m) E[m] = row2[m];   // win[0..31]
            const float* wp = wrow + c * 9;
            #pragma unroll
            for (int k = 0; k < 9; k += 2) {               // even taps
                float wv = wp[k];
                ull wv2 = pk2(wv, wv);
                int b0 = k >> 1;
                #pragma unroll
                for (int m = 0; m < 12; ++m) accE[m] = fma2(E[m + b0], wv2, accE[m]);
            }
            #pragma unroll
            for (int k = 1; k < 9; k += 2) {               // odd taps
                float wv = wp[k];
                ull wv2 = pk2(wv, wv);
                int b0 = (k + 1) >> 1;
                #pragma unroll
                for (int m = 0; m < 12; ++m) accO[m] = fma2(E[m + b0], wv2, accO[m]);
                acc0o += row[k] * wv;                      // output j=0, odd taps
            }
        }
        float accs[24], od[25];
        od[0] = acc0o;
        #pragma unroll
        for (int m = 0; m < 12; ++m) {
            float e0, e1; upk2(e0, e1, accE[m]);
            accs[2 * m] = e0; accs[2 * m + 1] = e1;
            float o0, o1; upk2(o0, o1, accO[m]);
            od[2 * m + 1] = o0; od[2 * m + 2] = o1;
        }
        #pragma unroll
        for (int j = 0; j < 24; ++j) {
            int h = h0 + j;
            if (h < 174) C[o * 176 + h] = rate50(accs[j] + od[j]);
        }
    }
    __syncthreads();

    // ---- stage 3: sum-pool(2)*1.1 + rate -> B (r3, stride 120, data at h+1) ----
    for (int idx = tid; idx < 32 * 87; idx += 256) {
        int o = idx / 87, h = idx - o * 87;
        float a = 1.1f * (C[o * 176 + 2 * h] + C[o * 176 + 2 * h + 1]);
        B[o * 120 + h + 1] = rate50(a);
    }
    // zero r3 pad cells (region previously held r1 data): index 0 and [88,120)
    // per row — disjoint from the writes above, so same phase is race-free.
    // Also zero reduction scratch (mx dead).
    if (tid < 32) {
        B[tid * 120] = 0.0f;
        #pragma unroll
        for (int j = 88; j < 120; ++j) B[tid * 120 + j] = 0.0f;
        A[tid] = 0.0f;
    }
    __syncthreads();

    // ---- stage 4: conv (32,32,7) pad 1 + rate -> C (r4, stride 88) ----
    {
        int o = tid >> 3;
        int h0 = (tid & 7) * 12;            // even -> aligned
        float bb = b3[o];
        ull bb2 = pk2(bb, bb);
        ull accE[6], accO[6];
        #pragma unroll
        for (int m = 0; m < 6; ++m) { accE[m] = bb2; accO[m] = 0ULL; }
        float acc0o = 0.0f;
        const float* wrow = W3s + o * 225;
        #pragma unroll 1
        for (int c = 0; c < 32; ++c) {
            const float* row = B + c * 120 + h0;
            const ull* row2 = (const ull*)row;
            ull E[9];
            #pragma unroll
            for (int m = 0; m < 9; ++m) E[m] = row2[m];    // win[0..17]
            const float* wp = wrow + c * 7;
            #pragma unroll
            for (int k = 0; k < 7; k += 2) {               // even taps
                float wv = wp[k];
                ull wv2 = pk2(wv, wv);
                int b0 = k >> 1;
                #pragma unroll
                for (int m = 0; m < 6; ++m) accE[m] = fma2(E[m + b0], wv2, accE[m]);
            }
            #pragma unroll
            for (int k = 1; k < 7; k += 2) {               // odd taps
                float wv = wp[k];
                ull wv2 = pk2(wv, wv);
                int b0 = (k + 1) >> 1;
                #pragma unroll
                for (int m = 0; m < 6; ++m) accO[m] = fma2(E[m + b0], wv2, accO[m]);
                acc0o += row[k] * wv;
            }
        }
        float accs[12], od[13];
        od[0] = acc0o;
        #pragma unroll
        for (int m = 0; m < 6; ++m) {
            float e0, e1; upk2(e0, e1, accE[m]);
            accs[2 * m] = e0; accs[2 * m + 1] = e1;
            float o0, o1; upk2(o0, o1, accO[m]);
            od[2 * m + 1] = o0; od[2 * m + 2] = o1;
        }
        #pragma unroll
        for (int j = 0; j < 12; ++j) {
            int h = h0 + j;
            if (h < 83) C[o * 88 + h] = rate50(accs[j] + od[j]);
        }
    }
    __syncthreads();

    // ---- stage 5: dense out[n,o] = sum_{c,h} r4[c,h]*wf[o,c,h] + bf[o] ----
    {
        float p0 = 0.f, p1 = 0.f, p2 = 0.f, p3 = 0.f;
        for (int idx = tid; idx < 32 * 83; idx += 256) {
            int c = idx / 83, h = idx - c * 83;
            float v = C[c * 88 + h];
            int wi = c * 83 + h;
            p0 += v * wf[wi];
            p1 += v * wf[wi + 2656];
            p2 += v * wf[wi + 2 * 2656];
            p3 += v * wf[wi + 3 * 2656];
        }
        #pragma unroll
        for (int off = 16; off; off >>= 1) {
            p0 += __shfl_down_sync(0xffffffffu, p0, off);
            p1 += __shfl_down_sync(0xffffffffu, p1, off);
            p2 += __shfl_down_sync(0xffffffffu, p2, off);
            p3 += __shfl_down_sync(0xffffffffu, p3, off);
        }
        int lane = tid & 31, wid = tid >> 5;
        if (lane == 0) {
            A[wid * 4 + 0] = p0;
            A[wid * 4 + 1] = p1;
            A[wid * 4 + 2] = p2;
            A[wid * 4 + 3] = p3;
        }
    }
    __syncthreads();
    if (tid < 4) {
        float s = bf[tid];
        #pragma unroll
        for (int w = 0; w < 8; ++w) s += A[w * 4 + tid];
        out[n * 4 + tid] = s;
    }
}

extern "C" void kernel_launch(void* const* d_in, const int* in_sizes, int n_in,
                              void* d_out, int out_size) {
    const float* x  = (const float*)d_in[0];
    const float* w1 = (const float*)d_in[1];
    const float* b1 = (const float*)d_in[2];
    const float* w2 = (const float*)d_in[3];
    const float* b2 = (const float*)d_in[4];
    const float* w3 = (const float*)d_in[5];
    const float* b3 = (const float*)d_in[6];
    const float* wf = (const float*)d_in[7];
    const float* bf = (const float*)d_in[8];
    float* out = (float*)d_out;

    cudaFuncSetAttribute(catnet_kernel,
                         cudaFuncAttributeMaxDynamicSharedMemorySize, SMEM_BYTES);

    int n = in_sizes[0] / (180 * 50);   // batch size (256)
    catnet_kernel<<<n, 256, SMEM_BYTES>>>(x, w1, b1, w2, b2, w3, b3, wf, bf, out);
}